// round 1
// baseline (speedup 1.0000x reference)
#include <cuda_runtime.h>
#include <math.h>
#include <stdio.h>

// Problem constants
constexpr int Bv = 8, Tv = 2048, Cv = 1024, NFv = 64;
constexpr int Mdim = Bv * Tv;          // 16384 rows
constexpr float EPS = 1e-6f;

// Scratch (device globals: no allocations allowed)
__device__ float g_q0[(size_t)Mdim * Cv];      // 64 MB
__device__ float g_q1[(size_t)Mdim * Cv];      // 64 MB
__device__ float g_v [(size_t)Mdim * Cv];      // 64 MB
__device__ float g_sc[(size_t)Mdim * 2 * NFv]; // 8 MB  (sin|cos features)

// ---------------------------------------------------------------------------
// Generic fp32 tiled GEMM: C = A @ B + bias
// BM=128, BN=128, BK=16, 256 threads, 8x8 microtile.
// AMODE 0: A plain (lda = Kdim). AMODE 1: A = q .* v elementwise (both lda=Kdim).
// SMODE 0: plain store to C0 (ldc = Ndim).
// SMODE 1: split store at column 1024 -> C0 (q) and C1 (v), both ldc=1024.
// All dims assumed divisible by tile sizes (true for this problem).
// ---------------------------------------------------------------------------
template<int AMODE, int SMODE>
__global__ void __launch_bounds__(256)
gemm128_kernel(const float* __restrict__ A, const float* __restrict__ A2,
               const float* __restrict__ Bm, const float* __restrict__ bias,
               float* __restrict__ C0, float* __restrict__ C1,
               int Ndim, int Kdim)
{
    __shared__ float As[16][128];
    __shared__ float Bs[16][128];

    const int bm = blockIdx.y * 128;
    const int bn = blockIdx.x * 128;
    const int tid = threadIdx.x;
    const int tr = tid >> 4;   // 0..15
    const int tc = tid & 15;   // 0..15

    float acc[8][8];
#pragma unroll
    for (int i = 0; i < 8; i++)
#pragma unroll
        for (int j = 0; j < 8; j++) acc[i][j] = 0.f;

    for (int k0 = 0; k0 < Kdim; k0 += 16) {
        // Load A tile (128 rows x 16 k): 512 float4, 2 per thread
#pragma unroll
        for (int l = 0; l < 2; l++) {
            int f = tid + l * 256;
            int row = f >> 2;
            int kq = (f & 3) * 4;
            size_t gidx = (size_t)(bm + row) * Kdim + k0 + kq;
            float4 av = *reinterpret_cast<const float4*>(&A[gidx]);
            if (AMODE == 1) {
                float4 vv = *reinterpret_cast<const float4*>(&A2[gidx]);
                av.x *= vv.x; av.y *= vv.y; av.z *= vv.z; av.w *= vv.w;
            }
            As[kq + 0][row] = av.x;
            As[kq + 1][row] = av.y;
            As[kq + 2][row] = av.z;
            As[kq + 3][row] = av.w;
        }
        // Load B tile (16 k x 128 n): 512 float4, 2 per thread
#pragma unroll
        for (int l = 0; l < 2; l++) {
            int f = tid + l * 256;
            int row = f >> 5;
            int nq = (f & 31) * 4;
            float4 bv = *reinterpret_cast<const float4*>(
                &Bm[(size_t)(k0 + row) * Ndim + bn + nq]);
            *reinterpret_cast<float4*>(&Bs[row][nq]) = bv;
        }
        __syncthreads();

#pragma unroll
        for (int k = 0; k < 16; k++) {
            float af[8], bf[8];
#pragma unroll
            for (int i = 0; i < 8; i++) af[i] = As[k][tr * 8 + i];
#pragma unroll
            for (int j = 0; j < 8; j++) bf[j] = Bs[k][tc * 8 + j];
#pragma unroll
            for (int i = 0; i < 8; i++)
#pragma unroll
                for (int j = 0; j < 8; j++) acc[i][j] += af[i] * bf[j];
        }
        __syncthreads();
    }

    // Epilogue
#pragma unroll
    for (int i = 0; i < 8; i++) {
        int r = bm + tr * 8 + i;
#pragma unroll
        for (int j = 0; j < 8; j += 4) {
            int c = bn + tc * 8 + j;
            float4 o;
            o.x = acc[i][j + 0] + bias[c + 0];
            o.y = acc[i][j + 1] + bias[c + 1];
            o.z = acc[i][j + 2] + bias[c + 2];
            o.w = acc[i][j + 3] + bias[c + 3];
            if (SMODE == 0) {
                *reinterpret_cast<float4*>(&C0[(size_t)r * Ndim + c]) = o;
            } else {
                if (c < 1024)
                    *reinterpret_cast<float4*>(&C0[(size_t)r * 1024 + c]) = o;
                else
                    *reinterpret_cast<float4*>(&C1[(size_t)r * 1024 + (c - 1024)]) = o;
            }
        }
    }
}

// ---------------------------------------------------------------------------
// Freq GEMM for one scan step:
//   f[r, c] = sum_k z[r,k] * freq_W[k,c] + freq_b[c],  c in [0,64)
//   z[r, k] = (k < 1024) ? prev(r,k) : q[r, k-1024]
//   prev(r,k) = (t >= n) ? q[r-n, k] : identity[k]    (t = r mod T)
//   sc[r, c]      = sinf(f)
//   sc[r, 64 + c] = cosf(f)
// BM=128, BN=64, BK=16, 128 threads, 8x8 microtile. Grid = M/128.
// ---------------------------------------------------------------------------
__global__ void __launch_bounds__(128)
gemm_freq_kernel(const float* __restrict__ q,
                 const float* __restrict__ freq_W,
                 const float* __restrict__ freq_b,
                 const float* __restrict__ identity,
                 float* __restrict__ sc, int n)
{
    __shared__ float As[16][128];
    __shared__ float Bs[16][64];

    const int bm = blockIdx.x * 128;
    const int tid = threadIdx.x;
    const int tr = tid >> 3;  // 0..15
    const int tc = tid & 7;   // 0..7

    float acc[8][8];
#pragma unroll
    for (int i = 0; i < 8; i++)
#pragma unroll
        for (int j = 0; j < 8; j++) acc[i][j] = 0.f;

    for (int k0 = 0; k0 < 2048; k0 += 16) {
        // Load implicit-A tile: 128 rows x 16 k = 512 float4, 4 per thread
#pragma unroll
        for (int l = 0; l < 4; l++) {
            int f = tid + l * 128;
            int row = f >> 2;
            int kq = (f & 3) * 4;
            int gr = bm + row;
            float4 av;
            if (k0 < 1024) {
                int t = gr & (Tv - 1);
                if (t >= n)
                    av = *reinterpret_cast<const float4*>(
                        &q[(size_t)(gr - n) * Cv + k0 + kq]);
                else
                    av = *reinterpret_cast<const float4*>(&identity[k0 + kq]);
            } else {
                av = *reinterpret_cast<const float4*>(
                    &q[(size_t)gr * Cv + (k0 - 1024) + kq]);
            }
            As[kq + 0][row] = av.x;
            As[kq + 1][row] = av.y;
            As[kq + 2][row] = av.z;
            As[kq + 3][row] = av.w;
        }
        // Load B tile: 16 x 64 = 256 float4, 2 per thread
#pragma unroll
        for (int l = 0; l < 2; l++) {
            int f = tid + l * 128;
            int row = f >> 4;
            int nq = (f & 15) * 4;
            float4 bv = *reinterpret_cast<const float4*>(
                &freq_W[(size_t)(k0 + row) * NFv + nq]);
            *reinterpret_cast<float4*>(&Bs[row][nq]) = bv;
        }
        __syncthreads();

#pragma unroll
        for (int k = 0; k < 16; k++) {
            float af[8], bf[8];
#pragma unroll
            for (int i = 0; i < 8; i++) af[i] = As[k][tr * 8 + i];
#pragma unroll
            for (int j = 0; j < 8; j++) bf[j] = Bs[k][tc * 8 + j];
#pragma unroll
            for (int i = 0; i < 8; i++)
#pragma unroll
                for (int j = 0; j < 8; j++) acc[i][j] += af[i] * bf[j];
        }
        __syncthreads();
    }

    // Epilogue: sin/cos, store to sc[r, 0:64]=sin, sc[r, 64:128]=cos
#pragma unroll
    for (int i = 0; i < 8; i++) {
        int r = bm + tr * 8 + i;
#pragma unroll
        for (int j = 0; j < 8; j++) {
            int c = tc * 8 + j;
            float fv = acc[i][j] + freq_b[c];
            sc[(size_t)r * 128 + c]      = sinf(fv);
            sc[(size_t)r * 128 + 64 + c] = cosf(fv);
        }
    }
}

// ---------------------------------------------------------------------------
// mmnorm: in-place per-row q /= (max|q| + EPS). Grid = M, 256 threads.
// ---------------------------------------------------------------------------
__global__ void __launch_bounds__(256)
mmnorm_kernel(float* __restrict__ q)
{
    int r = blockIdx.x;
    int tid = threadIdx.x;
    float4* row = reinterpret_cast<float4*>(q + (size_t)r * Cv);
    float4 v = row[tid];
    float m = fmaxf(fmaxf(fabsf(v.x), fabsf(v.y)), fmaxf(fabsf(v.z), fabsf(v.w)));
#pragma unroll
    for (int o = 16; o; o >>= 1) m = fmaxf(m, __shfl_xor_sync(0xffffffffu, m, o));
    __shared__ float wm[8];
    if ((tid & 31) == 0) wm[tid >> 5] = m;
    __syncthreads();
    float mm = wm[0];
#pragma unroll
    for (int i = 1; i < 8; i++) mm = fmaxf(mm, wm[i]);
    float inv = 1.0f / (mm + EPS);
    v.x *= inv; v.y *= inv; v.z *= inv; v.w *= inv;
    row[tid] = v;
}

// ---------------------------------------------------------------------------
extern "C" void kernel_launch(void* const* d_in, const int* in_sizes, int n_in,
                              void* d_out, int out_size)
{
    const float* x       = (const float*)d_in[0];
    const float* attn_W  = (const float*)d_in[1];
    const float* attn_b  = (const float*)d_in[2];
    const float* freq_W  = (const float*)d_in[3];
    const float* freq_b  = (const float*)d_in[4];
    const float* out_W   = (const float*)d_in[5];
    const float* out_b   = (const float*)d_in[6];
    const float* proj_W  = (const float*)d_in[7];
    const float* proj_b  = (const float*)d_in[8];
    const float* identity= (const float*)d_in[9];
    float* out = (float*)d_out;

    float *q0, *q1, *v, *sc;
    cudaGetSymbolAddress((void**)&q0, g_q0);
    cudaGetSymbolAddress((void**)&q1, g_q1);
    cudaGetSymbolAddress((void**)&v,  g_v);
    cudaGetSymbolAddress((void**)&sc, g_sc);

    // 1) qv = x @ attn_W + attn_b ; split into q (g_q0) and v (g_v)
    {
        dim3 grid(2048 / 128, Mdim / 128);
        gemm128_kernel<0, 1><<<grid, 256>>>(x, nullptr, attn_W, attn_b,
                                            q0, v, 2048, Cv);
    }

    // 2) scan: n = 1, 2, 4, ..., 1024 (11 iterations)
    float* qsrc = q0;
    float* qdst = q1;
    for (int n = 1; n < Tv; n <<= 1) {
        gemm_freq_kernel<<<Mdim / 128, 128>>>(qsrc, freq_W, freq_b, identity, sc, n);

        dim3 grid(Cv / 128, Mdim / 128);
        gemm128_kernel<0, 0><<<grid, 256>>>(sc, nullptr, out_W, out_b,
                                            qdst, nullptr, Cv, 128);

        mmnorm_kernel<<<Mdim, 256>>>(qdst);

        float* tmp = qsrc; qsrc = qdst; qdst = tmp;
    }
    // final q is in qsrc after the last swap

    // 3) out = (q .* v) @ proj_W + proj_b
    {
        dim3 grid(Cv / 128, Mdim / 128);
        gemm128_kernel<1, 0><<<grid, 256>>>(qsrc, v, proj_W, proj_b,
                                            out, nullptr, Cv, Cv);
    }
}

// round 2
// speedup vs baseline: 1.0168x; 1.0168x over previous
#include <cuda_runtime.h>
#include <math.h>

// Problem constants
constexpr int Tv = 2048, Cv = 1024;
constexpr int Mdim = 8 * 2048;   // 16384 rows
constexpr float EPS = 1e-6f;

// Scratch (device globals)
__device__ float g_q0[(size_t)Mdim * Cv];      // 64 MB
__device__ float g_q1[(size_t)Mdim * Cv];      // 64 MB
__device__ float g_v [(size_t)Mdim * Cv];      // 64 MB
__device__ float g_sc[(size_t)Mdim * 128];     // 8 MB (sin|cos)

// ---------------------------------------------------------------------------
// TF32 helpers
// ---------------------------------------------------------------------------
__device__ __forceinline__ unsigned f2tf(float x) {
    unsigned r; asm("cvt.rna.tf32.f32 %0, %1;" : "=r"(r) : "f"(x)); return r;
}
__device__ __forceinline__ void mma_tf32(float d[4], const unsigned a[4], const unsigned b[2]) {
    asm volatile("mma.sync.aligned.m16n8k8.row.col.f32.tf32.tf32.f32 "
        "{%0,%1,%2,%3},{%4,%5,%6,%7},{%8,%9},{%0,%1,%2,%3};"
        : "+f"(d[0]), "+f"(d[1]), "+f"(d[2]), "+f"(d[3])
        : "r"(a[0]), "r"(a[1]), "r"(a[2]), "r"(a[3]), "r"(b[0]), "r"(b[1]));
}

// ---------------------------------------------------------------------------
// Main MMA GEMM: C = A @ B + bias.  BM=128, BN=128, BK=16, 256 thr (8 warps 2x4).
// Fragment-packed SMEM: A [s][mt][lane][4regs] (LDS.128), B [s][nt][lane][2regs].
// NSPLIT: 1 = tf32, 3 = tf32x3 (hi/lo split).
// AMODE 1: A = A .* A2 elementwise.  SMODE 1: split store at col 1024 -> C0/C1.
// ---------------------------------------------------------------------------
template<int NSPLIT, int AMODE, int SMODE>
__global__ void __launch_bounds__(256)
mma_gemm_kernel(const float* __restrict__ A, const float* __restrict__ A2,
                const float* __restrict__ Bm, const float* __restrict__ bias,
                float* __restrict__ C0, float* __restrict__ C1,
                int Ndim, int Kdim)
{
    __shared__ float AsP[2][2048];   // 2 s * 8 mt * 32 lanes * 4 regs
    __shared__ float BsP[2][2048];   // 2 s * 16 nt * 32 lanes * 2 regs

    const int tid = threadIdx.x;
    const int warp = tid >> 5, lane = tid & 31;
    const int bm = blockIdx.y * 128, bn = blockIdx.x * 128;
    const int wmt = (warp >> 2) * 4;   // warp's first m-tile (16 rows each)
    const int wnt = (warp & 3) * 4;    // warp's first n-tile (8 cols each)

    float acc[4][4][4];
#pragma unroll
    for (int i = 0; i < 4; i++)
#pragma unroll
        for (int j = 0; j < 4; j++)
#pragma unroll
            for (int r = 0; r < 4; r++) acc[i][j][r] = 0.f;

    float4 aR[2], bR[2];

    auto gload = [&](int k0) {
#pragma unroll
        for (int l = 0; l < 2; l++) {
            int f = tid + l * 256;
            int m = f >> 2, jq = f & 3;
            size_t gi = (size_t)(bm + m) * Kdim + k0 + 4 * jq;
            float4 av = *reinterpret_cast<const float4*>(&A[gi]);
            if (AMODE == 1) {
                float4 vv = *reinterpret_cast<const float4*>(&A2[gi]);
                av.x *= vv.x; av.y *= vv.y; av.z *= vv.z; av.w *= vv.w;
            }
            aR[l] = av;
            int kr = f >> 5, n0 = (f & 31) * 4;
            bR[l] = *reinterpret_cast<const float4*>(&Bm[(size_t)(k0 + kr) * Ndim + bn + n0]);
        }
    };

    gload(0);
    const int KT = Kdim >> 4;

    for (int kt = 0; kt < KT; kt++) {
        const int buf = kt & 1;
        // fragment-packed STS
#pragma unroll
        for (int l = 0; l < 2; l++) {
            int f = tid + l * 256;
            int m = f >> 2, jq = f & 3;
            int s = jq >> 1, rhi = jq & 1;
            int mt = m >> 4, mm = m & 15, rlo = mm >> 3, gg = mm & 7;
            int r = rlo + 2 * rhi;
            int base = (s * 8 + mt) * 32 + gg * 4;
            AsP[buf][(base + 0) * 4 + r] = aR[l].x;
            AsP[buf][(base + 1) * 4 + r] = aR[l].y;
            AsP[buf][(base + 2) * 4 + r] = aR[l].z;
            AsP[buf][(base + 3) * 4 + r] = aR[l].w;

            int kr = f >> 5, n0 = (f & 31) * 4;
            int s2 = kr >> 3, kk = kr & 7, cc = kk & 3, rb = kk >> 2;
            float bv[4] = {bR[l].x, bR[l].y, bR[l].z, bR[l].w};
#pragma unroll
            for (int e = 0; e < 4; e++) {
                int n = n0 + e, nt = n >> 3, g2 = n & 7;
                BsP[buf][((s2 * 16 + nt) * 32 + g2 * 4 + cc) * 2 + rb] = bv[e];
            }
        }
        __syncthreads();
        if (kt + 1 < KT) gload((kt + 1) * 16);

        // compute
#pragma unroll
        for (int s = 0; s < 2; s++) {
            unsigned ahi[4][4], alo[4][4], bhi[4][2], blo[4][2];
#pragma unroll
            for (int i = 0; i < 4; i++) {
                float4 av = *reinterpret_cast<const float4*>(
                    &AsP[buf][((s * 8 + wmt + i) * 32 + lane) * 4]);
                float af[4] = {av.x, av.y, av.z, av.w};
#pragma unroll
                for (int r = 0; r < 4; r++) {
                    ahi[i][r] = f2tf(af[r]);
                    if (NSPLIT == 3)
                        alo[i][r] = f2tf(af[r] - __uint_as_float(ahi[i][r]));
                }
            }
#pragma unroll
            for (int j = 0; j < 4; j++) {
                float2 bv = *reinterpret_cast<const float2*>(
                    &BsP[buf][((s * 16 + wnt + j) * 32 + lane) * 2]);
                bhi[j][0] = f2tf(bv.x); bhi[j][1] = f2tf(bv.y);
                if (NSPLIT == 3) {
                    blo[j][0] = f2tf(bv.x - __uint_as_float(bhi[j][0]));
                    blo[j][1] = f2tf(bv.y - __uint_as_float(bhi[j][1]));
                }
            }
#pragma unroll
            for (int i = 0; i < 4; i++)
#pragma unroll
                for (int j = 0; j < 4; j++) {
                    if (NSPLIT == 3) {
                        mma_tf32(acc[i][j], alo[i], bhi[j]);
                        mma_tf32(acc[i][j], ahi[i], blo[j]);
                    }
                    mma_tf32(acc[i][j], ahi[i], bhi[j]);
                }
        }
        __syncthreads();
    }

    // epilogue
    const int g = lane >> 2, c = lane & 3;
#pragma unroll
    for (int i = 0; i < 4; i++) {
        int r0 = bm + (wmt + i) * 16 + g;
#pragma unroll
        for (int j = 0; j < 4; j++) {
            int cn = bn + (wnt + j) * 8 + 2 * c;
            float bx = bias[cn], by = bias[cn + 1];
            float2 v0 = make_float2(acc[i][j][0] + bx, acc[i][j][1] + by);
            float2 v1 = make_float2(acc[i][j][2] + bx, acc[i][j][3] + by);
            if (SMODE == 0) {
                *reinterpret_cast<float2*>(&C0[(size_t)r0 * Ndim + cn]) = v0;
                *reinterpret_cast<float2*>(&C0[(size_t)(r0 + 8) * Ndim + cn]) = v1;
            } else {
                float* Ct = (bn < 1024) ? C0 : C1;
                int c2 = cn - ((bn < 1024) ? 0 : 1024);
                *reinterpret_cast<float2*>(&Ct[(size_t)r0 * 1024 + c2]) = v0;
                *reinterpret_cast<float2*>(&Ct[(size_t)(r0 + 8) * 1024 + c2]) = v1;
            }
        }
    }
}

// ---------------------------------------------------------------------------
// Freq GEMM (scan step): f = [prev | q] @ freq_W + freq_b; sc = [sin f | cos f].
// BM=64, BN=64, BK=16, 128 thr (4 warps 2x2, warp tile 32x32). tf32x3.
// ---------------------------------------------------------------------------
template<int NSPLIT>
__global__ void __launch_bounds__(128)
freq_mma_kernel(const float* __restrict__ q, const float* __restrict__ freq_W,
                const float* __restrict__ freq_b, const float* __restrict__ identity,
                float* __restrict__ sc, int n)
{
    __shared__ float AsP[2][1024];   // 2 s * 4 mt * 32 * 4
    __shared__ float BsP[2][1024];   // 2 s * 8 nt * 32 * 2

    const int tid = threadIdx.x;
    const int warp = tid >> 5, lane = tid & 31;
    const int bm = blockIdx.x * 64;
    const int wmt = (warp >> 1) * 2;   // 2 m-tiles per warp
    const int wnt = (warp & 1) * 4;    // 4 n-tiles per warp

    float acc[2][4][4];
#pragma unroll
    for (int i = 0; i < 2; i++)
#pragma unroll
        for (int j = 0; j < 4; j++)
#pragma unroll
            for (int r = 0; r < 4; r++) acc[i][j][r] = 0.f;

    float4 aR[2], bR[2];

    auto gload = [&](int k0) {
#pragma unroll
        for (int l = 0; l < 2; l++) {
            int f = tid + l * 128;
            int m = f >> 2, jq = f & 3;
            int gr = bm + m;
            int kg = k0 + 4 * jq;
            const float* src;
            if (kg < 1024) {
                int t = gr & (Tv - 1);
                src = (t >= n) ? &q[(size_t)(gr - n) * Cv + kg] : &identity[kg];
            } else {
                src = &q[(size_t)gr * Cv + (kg - 1024)];
            }
            aR[l] = *reinterpret_cast<const float4*>(src);
            int kr = f >> 4, n0 = (f & 15) * 4;
            bR[l] = *reinterpret_cast<const float4*>(&freq_W[(size_t)(k0 + kr) * 64 + n0]);
        }
    };

    gload(0);
    const int KT = 2048 >> 4;   // 128

    for (int kt = 0; kt < KT; kt++) {
        const int buf = kt & 1;
#pragma unroll
        for (int l = 0; l < 2; l++) {
            int f = tid + l * 128;
            int m = f >> 2, jq = f & 3;
            int s = jq >> 1, rhi = jq & 1;
            int mt = m >> 4, mm = m & 15, rlo = mm >> 3, gg = mm & 7;
            int r = rlo + 2 * rhi;
            int base = (s * 4 + mt) * 32 + gg * 4;
            AsP[buf][(base + 0) * 4 + r] = aR[l].x;
            AsP[buf][(base + 1) * 4 + r] = aR[l].y;
            AsP[buf][(base + 2) * 4 + r] = aR[l].z;
            AsP[buf][(base + 3) * 4 + r] = aR[l].w;

            int kr = f >> 4, n0 = (f & 15) * 4;
            int s2 = kr >> 3, kk = kr & 7, cc = kk & 3, rb = kk >> 2;
            float bv[4] = {bR[l].x, bR[l].y, bR[l].z, bR[l].w};
#pragma unroll
            for (int e = 0; e < 4; e++) {
                int nn = n0 + e, nt = nn >> 3, g2 = nn & 7;
                BsP[buf][((s2 * 8 + nt) * 32 + g2 * 4 + cc) * 2 + rb] = bv[e];
            }
        }
        __syncthreads();
        if (kt + 1 < KT) gload((kt + 1) * 16);

#pragma unroll
        for (int s = 0; s < 2; s++) {
            unsigned ahi[2][4], alo[2][4], bhi[4][2], blo[4][2];
#pragma unroll
            for (int i = 0; i < 2; i++) {
                float4 av = *reinterpret_cast<const float4*>(
                    &AsP[buf][((s * 4 + wmt + i) * 32 + lane) * 4]);
                float af[4] = {av.x, av.y, av.z, av.w};
#pragma unroll
                for (int r = 0; r < 4; r++) {
                    ahi[i][r] = f2tf(af[r]);
                    if (NSPLIT == 3)
                        alo[i][r] = f2tf(af[r] - __uint_as_float(ahi[i][r]));
                }
            }
#pragma unroll
            for (int j = 0; j < 4; j++) {
                float2 bv = *reinterpret_cast<const float2*>(
                    &BsP[buf][((s * 8 + wnt + j) * 32 + lane) * 2]);
                bhi[j][0] = f2tf(bv.x); bhi[j][1] = f2tf(bv.y);
                if (NSPLIT == 3) {
                    blo[j][0] = f2tf(bv.x - __uint_as_float(bhi[j][0]));
                    blo[j][1] = f2tf(bv.y - __uint_as_float(bhi[j][1]));
                }
            }
#pragma unroll
            for (int i = 0; i < 2; i++)
#pragma unroll
                for (int j = 0; j < 4; j++) {
                    if (NSPLIT == 3) {
                        mma_tf32(acc[i][j], alo[i], bhi[j]);
                        mma_tf32(acc[i][j], ahi[i], blo[j]);
                    }
                    mma_tf32(acc[i][j], ahi[i], bhi[j]);
                }
        }
        __syncthreads();
    }

    // epilogue: sin/cos
    const int g = lane >> 2, c = lane & 3;
#pragma unroll
    for (int i = 0; i < 2; i++) {
        int r0 = bm + (wmt + i) * 16 + g;
#pragma unroll
        for (int j = 0; j < 4; j++) {
            int cn = (wnt + j) * 8 + 2 * c;
            float bx = freq_b[cn], by = freq_b[cn + 1];
            float f0 = acc[i][j][0] + bx, f1 = acc[i][j][1] + by;
            float f2v = acc[i][j][2] + bx, f3v = acc[i][j][3] + by;
            *reinterpret_cast<float2*>(&sc[(size_t)r0 * 128 + cn]) =
                make_float2(sinf(f0), sinf(f1));
            *reinterpret_cast<float2*>(&sc[(size_t)r0 * 128 + 64 + cn]) =
                make_float2(cosf(f0), cosf(f1));
            *reinterpret_cast<float2*>(&sc[(size_t)(r0 + 8) * 128 + cn]) =
                make_float2(sinf(f2v), sinf(f3v));
            *reinterpret_cast<float2*>(&sc[(size_t)(r0 + 8) * 128 + 64 + cn]) =
                make_float2(cosf(f2v), cosf(f3v));
        }
    }
}

// ---------------------------------------------------------------------------
// mmnorm: in-place per-row q /= (max|q| + EPS). Already at memory floor.
// ---------------------------------------------------------------------------
__global__ void __launch_bounds__(256)
mmnorm_kernel(float* __restrict__ q)
{
    int r = blockIdx.x;
    int tid = threadIdx.x;
    float4* row = reinterpret_cast<float4*>(q + (size_t)r * Cv);
    float4 v = row[tid];
    float m = fmaxf(fmaxf(fabsf(v.x), fabsf(v.y)), fmaxf(fabsf(v.z), fabsf(v.w)));
#pragma unroll
    for (int o = 16; o; o >>= 1) m = fmaxf(m, __shfl_xor_sync(0xffffffffu, m, o));
    __shared__ float wm[8];
    if ((tid & 31) == 0) wm[tid >> 5] = m;
    __syncthreads();
    float mm = wm[0];
#pragma unroll
    for (int i = 1; i < 8; i++) mm = fmaxf(mm, wm[i]);
    float inv = 1.0f / (mm + EPS);
    v.x *= inv; v.y *= inv; v.z *= inv; v.w *= inv;
    row[tid] = v;
}

// ---------------------------------------------------------------------------
extern "C" void kernel_launch(void* const* d_in, const int* in_sizes, int n_in,
                              void* d_out, int out_size)
{
    const float* x        = (const float*)d_in[0];
    const float* attn_W   = (const float*)d_in[1];
    const float* attn_b   = (const float*)d_in[2];
    const float* freq_W   = (const float*)d_in[3];
    const float* freq_b   = (const float*)d_in[4];
    const float* out_W    = (const float*)d_in[5];
    const float* out_b    = (const float*)d_in[6];
    const float* proj_W   = (const float*)d_in[7];
    const float* proj_b   = (const float*)d_in[8];
    const float* identity = (const float*)d_in[9];
    float* out = (float*)d_out;

    float *q0, *q1, *v, *sc;
    cudaGetSymbolAddress((void**)&q0, g_q0);
    cudaGetSymbolAddress((void**)&q1, g_q1);
    cudaGetSymbolAddress((void**)&v,  g_v);
    cudaGetSymbolAddress((void**)&sc, g_sc);

    // 1) qv = x @ attn_W + attn_b -> split q | v   (tf32x1)
    {
        dim3 grid(2048 / 128, Mdim / 128);
        mma_gemm_kernel<1, 0, 1><<<grid, 256>>>(x, nullptr, attn_W, attn_b,
                                                q0, v, 2048, Cv);
    }

    // 2) scan (11 iterations), tf32x3 for accuracy
    float* qsrc = q0;
    float* qdst = q1;
    for (int n = 1; n < Tv; n <<= 1) {
        freq_mma_kernel<3><<<Mdim / 64, 128>>>(qsrc, freq_W, freq_b, identity, sc, n);

        dim3 grid(Cv / 128, Mdim / 128);
        mma_gemm_kernel<3, 0, 0><<<grid, 256>>>(sc, nullptr, out_W, out_b,
                                                qdst, nullptr, Cv, 128);

        mmnorm_kernel<<<Mdim, 256>>>(qdst);

        float* tmp = qsrc; qsrc = qdst; qdst = tmp;
    }

    // 3) out = (q .* v) @ proj_W + proj_b   (tf32x1)
    {
        dim3 grid(Cv / 128, Mdim / 128);
        mma_gemm_kernel<1, 1, 0><<<grid, 256>>>(qsrc, v, proj_W, proj_b,
                                                out, nullptr, Cv, Cv);
    }
}